// round 16
// baseline (speedup 1.0000x reference)
#include <cuda_runtime.h>
#include <cuda_bf16.h>
#include <math.h>

typedef unsigned int u32;
typedef unsigned long long ull;

// ---------------------------------------------------------------------------
// Scratch (device globals; no allocation anywhere)
// ---------------------------------------------------------------------------
static __device__ __align__(16) float g_bufA[33554432];   // 134 MB
static __device__ __align__(16) float g_bufB[16777216];   //  67 MB
static __device__ int   g_idx[8192];
static __device__ float g_e2[1024];
static __device__ __align__(16) u32 g_wt[4005888];  // enc u64 + dec u32 weights

// packed f32x2 helpers (scalar paths)
__device__ __forceinline__ void ffma2(ull& d, ull a, ull b) {
    asm("fma.rn.f32x2 %0, %1, %2, %0;" : "+l"(d) : "l"(a), "l"(b));
}
__device__ __forceinline__ ull pack2(float a) {
    ull r; unsigned int ai = __float_as_uint(a);
    asm("mov.b64 %0, {%1, %1};" : "=l"(r) : "r"(ai));
    return r;
}
__device__ __forceinline__ float2 upk(ull v) {
    union { ull u; float2 f; } c; c.u = v; return c.f;
}
__device__ __forceinline__ u32 packbf(float v0, float v1) {
    __nv_bfloat162 t = __floats2bfloat162_rn(v0, v1);
    u32 r; memcpy(&r, &t, 4); return r;
}
// split two f32 into (hi bf16x2, lo bf16x2) packed in one u64
__device__ __forceinline__ ull packsplit(float v0, float v1) {
    __nv_bfloat162 h = __floats2bfloat162_rn(v0, v1);
    float r0 = v0 - __bfloat162float(h.x);
    float r1 = v1 - __bfloat162float(h.y);
    u32 hi; memcpy(&hi, &h, 4);
    u32 lo = packbf(r0, r1);
    return (ull)hi | ((ull)lo << 32);
}
// m16n8k16 row.col bf16 MMA, fp32 accum. (a0,a1,b0)=k0-7, (a2,a3,b1)=k8-15.
__device__ __forceinline__ void mma16(float* c, u32 a0, u32 a1, u32 a2, u32 a3,
                                      u32 b0, u32 b1) {
    asm("mma.sync.aligned.m16n8k16.row.col.f32.bf16.bf16.f32 "
        "{%0,%1,%2,%3}, {%4,%5,%6,%7}, {%8,%9}, {%0,%1,%2,%3};"
        : "+f"(c[0]), "+f"(c[1]), "+f"(c[2]), "+f"(c[3])
        : "r"(a0), "r"(a1), "r"(a2), "r"(a3), "r"(b0), "r"(b1));
}
__device__ __forceinline__ void cp8(void* dst, const void* src, bool ok) {
    u32 da = (u32)__cvta_generic_to_shared(dst);
    asm volatile("cp.async.ca.shared.global [%0], [%1], 8, %2;\n"
                 :: "r"(da), "l"(src), "r"(ok ? 8 : 0));
}
__device__ __forceinline__ void cp16(void* dst, const void* src) {
    u32 da = (u32)__cvta_generic_to_shared(dst);
    asm volatile("cp.async.ca.shared.global [%0], [%1], 16;\n"
                 :: "r"(da), "l"(src));
}

// ---------------------------------------------------------------------------
// Encoder weight transpose -> u64 (hi,lo), layout [t][cout][cp]
// ---------------------------------------------------------------------------
__global__ void wtrans_kernel(const float* __restrict__ w, ull* __restrict__ dst,
                              int Cin, int Cout, int CPG)
{
    const int S = 16 * CPG * Cout;
    int idx = blockIdx.x * 256 + threadIdx.x;
    if (idx >= S) return;
    int cp = idx % CPG;
    int rest = idx / CPG;
    int co = rest % Cout;
    int t  = rest / Cout;
    int ci0 = 2 * cp;
    float v0 = (ci0     < Cin) ? w[((long)co * Cin + ci0    ) * 16 + t] : 0.f;
    float v1 = (ci0 + 1 < Cin) ? w[((long)co * Cin + ci0 + 1) * 16 + t] : 0.f;
    dst[idx] = packsplit(v0, v1);
}

// ---------------------------------------------------------------------------
// Decoder weight transpose (R11 layout): u32 hi at [t][cp][coutP], lo at +S
// ---------------------------------------------------------------------------
__global__ void wtrans_dec_kernel(const float* __restrict__ w, u32* __restrict__ dst,
                                  int Cin, int Cout, int CoutP, int CPG)
{
    const int S = 16 * CPG * CoutP;
    int idx = blockIdx.x * 256 + threadIdx.x;
    if (idx >= S) return;
    int co = idx % CoutP;
    int rest = idx / CoutP;
    int cp = rest % CPG;
    int t  = rest / CPG;
    int ci0 = 2 * cp;
    float v0 = 0.f, v1 = 0.f;
    if (co < Cout) {
        if (ci0     < Cin) v0 = w[((long)ci0       * Cout + co) * 16 + t];
        if (ci0 + 1 < Cin) v1 = w[((long)(ci0 + 1) * Cout + co) * 16 + t];
    }
    ull p = packsplit(v0, v1);
    dst[idx]     = (u32)p;
    dst[S + idx] = (u32)(p >> 32);
}

// ---------------------------------------------------------------------------
// Encoder conv (unchanged from R15 best)
// ---------------------------------------------------------------------------
template<bool IN_PACKED, bool OUT_PACKED>
__global__ __launch_bounds__(256)
void conv_enc_mma(const void* __restrict__ in_, const ull* __restrict__ wt,
                  const float* __restrict__ bias, void* __restrict__ out_,
                  int Cin, int Hin, int Win, int Cout, int CPG)
{
    extern __shared__ ull smdyn[];
    ull* a_s = smdyn;                   // 2 bufs x 2448 u64
    ull* w_s = smdyn + 4896;            // 2 bufs x 4096 u64

    const int Hout = Hin >> 1, Wout = Win >> 1;
    const int tiles_x = Wout >> 4;
    const int tx = blockIdx.x % tiles_x;
    const int ty = blockIdx.x / tiles_x;
    const int OX0 = tx * 16, OY0 = ty * 8;
    const int co0 = blockIdx.y * 64;
    const int b   = blockIdx.z;

    const int tid  = threadIdx.x;
    const int wid  = tid >> 5;
    const int lane = tid & 31;
    const int wm   = wid & 3;
    const int wn   = wid >> 2;
    const int l4   = lane >> 2;
    const int lm4  = lane & 3;

    float acc[2][4][4];
    #pragma unroll
    for (int rh = 0; rh < 2; rh++)
        #pragma unroll
        for (int nf = 0; nf < 4; nf++)
            #pragma unroll
            for (int c = 0; c < 4; c++) acc[rh][nf][c] = 0.f;

    const int nChunk = CPG >> 2;
    const long HW = (long)Hin * Win;

    auto stage_w = [&](int buf, int cic) {
        #pragma unroll 1
        for (int idx = tid; idx < 2048; idx += 256) {
            int seg = idx & 1;
            int co  = (idx >> 1) & 63;
            int t   = idx >> 7;
            const ull* src = &wt[((long)t * Cout + co0 + co) * CPG + cic * 4 + seg * 2];
            cp16(&w_s[buf * 4096 + (t * 64 + co) * 4 + seg * 2], src);
        }
    };
    auto stage_a = [&](int buf, int cic) {
        const ull* pbase = (const ull*)in_ + ((long)b * CPG + cic * 4) * HW;
        #pragma unroll 1
        for (int y = wid; y < 18; y += 8) {
            const int gy = 2 * OY0 - 1 + y;
            const bool okY = (gy >= 0) && (gy < Hin);
            const ull* prow = pbase + (long)gy * Win;
            ull* drow = &a_s[buf * 2448 + y * 68];
            #pragma unroll 1
            for (int e = lane; e < 136; e += 32) {
                int xs = e >> 2, cp = e & 3;
                int gx = 2 * OX0 - 1 + xs;
                bool ok = okY && (gx >= 0) && (gx < Win);
                const ull* src = ok ? (prow + cp * HW + gx) : (const ull*)in_;
                cp8(drow + (xs & 1) * 1224 + (xs >> 1) * 4 + cp, src, ok);
            }
        }
    };
    auto compute_chunk = [&](int buf) {
        const ull* wb = &w_s[buf * 4096 + lm4];
        const ull* abase = &a_s[buf * 2448 + lm4];
        #pragma unroll
        for (int ky = 0; ky < 4; ky++) {
            #pragma unroll
            for (int par = 0; par < 2; par++) {
                const int t0 = ky * 4 + par, t1 = t0 + 2;
                u32 bh0[4], bh1[4], bl0[4], bl1[4];
                #pragma unroll
                for (int nf = 0; nf < 4; nf++) {
                    const int coi = wn * 32 + nf * 8 + l4;
                    ull q0 = wb[(t0 * 64 + coi) * 4];
                    ull q1 = wb[(t1 * 64 + coi) * 4];
                    bh0[nf] = (u32)q0; bl0[nf] = (u32)(q0 >> 32);
                    bh1[nf] = (u32)q1; bl1[nf] = (u32)(q1 >> 32);
                }
                #pragma unroll
                for (int rh = 0; rh < 2; rh++) {
                    const int y = 4 * wm + 2 * rh + ky;
                    const ull* ab = abase + par * 1224 + y * 68;
                    ull p00 = ab[(l4    ) * 4];
                    ull p01 = ab[(l4 + 8) * 4];
                    ull p10 = ab[(l4 + 1) * 4];
                    ull p11 = ab[(l4 + 9) * 4];
                    u32 ah0 = (u32)p00, al0 = (u32)(p00 >> 32);
                    u32 ah1 = (u32)p01, al1 = (u32)(p01 >> 32);
                    u32 ah2 = (u32)p10, al2 = (u32)(p10 >> 32);
                    u32 ah3 = (u32)p11, al3 = (u32)(p11 >> 32);
                    #pragma unroll
                    for (int nf = 0; nf < 4; nf++)
                        mma16(acc[rh][nf], ah0, ah1, ah2, ah3, bh0[nf], bh1[nf]);
                    #pragma unroll
                    for (int nf = 0; nf < 4; nf++)
                        mma16(acc[rh][nf], ah0, ah1, ah2, ah3, bl0[nf], bl1[nf]);
                    #pragma unroll
                    for (int nf = 0; nf < 4; nf++)
                        mma16(acc[rh][nf], al0, al1, al2, al3, bh0[nf], bh1[nf]);
                }
            }
        }
    };

    if (IN_PACKED) {
        stage_a(0, 0); stage_w(0, 0);
        asm volatile("cp.async.commit_group;\n" ::: "memory");
        #pragma unroll 1
        for (int cic = 0; cic < nChunk; cic++) {
            if (cic + 1 < nChunk) {
                stage_a((cic + 1) & 1, cic + 1);
                stage_w((cic + 1) & 1, cic + 1);
                asm volatile("cp.async.commit_group;\n" ::: "memory");
                asm volatile("cp.async.wait_group 1;\n" ::: "memory");
            } else {
                asm volatile("cp.async.wait_group 0;\n" ::: "memory");
            }
            __syncthreads();
            compute_chunk(cic & 1);
            __syncthreads();
        }
    } else {
        stage_w(0, 0);
        asm volatile("cp.async.commit_group;\n" ::: "memory");
        const float* in = (const float*)in_;
        const long inB = (long)b * Cin * HW;
        #pragma unroll 1
        for (int y = wid; y < 18; y += 8) {
            const int gy = 2 * OY0 - 1 + y;
            const bool okY = (gy >= 0) && (gy < Hin);
            ull* drow = &a_s[y * 68];
            #pragma unroll 1
            for (int e = lane; e < 136; e += 32) {
                int xs = e >> 2, cp = e & 3;
                int gx = 2 * OX0 - 1 + xs;
                int ci0 = 2 * cp;
                float v0 = 0.f, v1 = 0.f;
                if (okY && gx >= 0 && gx < Win) {
                    if (ci0     < Cin) v0 = in[inB + (long)ci0       * HW + (long)gy * Win + gx];
                    if (ci0 + 1 < Cin) v1 = in[inB + (long)(ci0 + 1) * HW + (long)gy * Win + gx];
                }
                drow[(xs & 1) * 1224 + (xs >> 1) * 4 + cp] = packsplit(v0, v1);
            }
        }
        asm volatile("cp.async.wait_group 0;\n" ::: "memory");
        __syncthreads();
        compute_chunk(0);
    }

    const int ox0l = OX0 + l4;
    #pragma unroll
    for (int rh = 0; rh < 2; rh++) {
        const int oy = OY0 + 2 * wm + rh;
        if (OUT_PACKED) {
            ull* po = (ull*)out_;
            const int CPT = Cout >> 1;
            #pragma unroll
            for (int nf = 0; nf < 4; nf++) {
                const int cob = co0 + wn * 32 + nf * 8 + 2 * lm4;
                const float b0 = bias[cob], b1 = bias[cob + 1];
                const long rowb = (((long)b * CPT + (cob >> 1)) * Hout + oy) * Wout;
                po[rowb + ox0l]     = packsplit(fmaxf(acc[rh][nf][0] + b0, 0.f),
                                                fmaxf(acc[rh][nf][1] + b1, 0.f));
                po[rowb + ox0l + 8] = packsplit(fmaxf(acc[rh][nf][2] + b0, 0.f),
                                                fmaxf(acc[rh][nf][3] + b1, 0.f));
            }
        } else {
            float* out = (float*)out_;
            const long outB = (long)b * Cout * Hout * Wout;
            #pragma unroll
            for (int nf = 0; nf < 4; nf++) {
                const int cob = co0 + wn * 32 + nf * 8 + 2 * lm4;
                const float b0 = bias[cob], b1 = bias[cob + 1];
                float* o0 = &out[outB + ((long)cob       * Hout + oy) * Wout];
                float* o1 = &out[outB + ((long)(cob + 1) * Hout + oy) * Wout];
                o0[ox0l]     = fmaxf(acc[rh][nf][0] + b0, 0.f);
                o1[ox0l]     = fmaxf(acc[rh][nf][1] + b1, 0.f);
                o0[ox0l + 8] = fmaxf(acc[rh][nf][2] + b0, 0.f);
                o1[ox0l + 8] = fmaxf(acc[rh][nf][3] + b1, 0.f);
            }
        }
    }
}

// ---------------------------------------------------------------------------
// ConvTranspose: 8 warps = 4 parities x 2 cout-halves; each warp computes
// BOTH input rows -> W fragments reused across rows (wf/MMA 1.67 -> 1.33-).
// A smem: u64 [buf][r4][c18][cp4]; W: u32 [buf][hl2][t16][cp4][72]
// ---------------------------------------------------------------------------
template<bool OUT_PACKED>
__global__ __launch_bounds__(256)
void convt_mma(const void* __restrict__ in_, const u32* __restrict__ wt,
               const float* __restrict__ bias, void* __restrict__ out_,
               int Cin, int Hin, int Win, int Cout, int CoutP, int CPG)
{
    extern __shared__ ull smdyn[];
    ull* a_s = smdyn;                   // 2 bufs x 288 u64
    u32* w_s = (u32*)(smdyn + 576);     // 2 bufs x 9216 u32

    const int Hout = Hin * 2, Wout = Win * 2;
    const int tiles_x = Win >> 4;
    const int tx = blockIdx.x % tiles_x;
    const int ry = blockIdx.x / tiles_x;
    const int X0 = tx * 16, R0 = ry * 2;
    const int co0 = blockIdx.y * 64;
    const int b   = blockIdx.z;

    const int tid  = threadIdx.x;
    const int wid  = tid >> 5;
    const int lane = tid & 31;
    const int par  = wid & 3;          // parity class
    const int wn   = wid >> 2;         // cout half (32 couts)
    const int py   = par & 1;
    const int px   = par >> 1;
    const int l4   = lane >> 2;
    const int lm4  = lane & 3;

    const u32* wt_lo = wt + 16 * CPG * CoutP;

    float acc[2][4][4];                // [input row][nf][frag]
    #pragma unroll
    for (int rh = 0; rh < 2; rh++)
        #pragma unroll
        for (int nf = 0; nf < 4; nf++)
            #pragma unroll
            for (int c = 0; c < 4; c++) acc[rh][nf][c] = 0.f;

    const int nChunk = CPG >> 2;
    const int pc0 = (px == 0) ? 1 : 2;
    const int pc1 = (px == 0) ? 0 : 1;
    const long HW = (long)Hin * Win;

    auto stage = [&](int buf, int cic) {
        const ull* pbase = (const ull*)in_ + ((long)b * CPG + cic * 4) * HW;
        {
            const int r = wid & 3;
            const int gy = R0 - 1 + r;
            const bool okY = (gy >= 0) && (gy < Hin);
            const ull* prow = pbase + (long)gy * Win;
            ull* drow = &a_s[buf * 288 + r * 72];
            #pragma unroll 1
            for (int e = (wid >> 2) * 32 + lane; e < 72; e += 64) {
                int cp = e & 3, c = e >> 2;
                int gx = X0 - 1 + c;
                bool ok = okY && (gx >= 0) && (gx < Win);
                const ull* src = ok ? (prow + cp * HW + gx) : (const ull*)in_;
                cp8(drow + c * 4 + cp, src, ok);
            }
        }
        #pragma unroll 1
        for (int idx = tid; idx < 2048; idx += 256) {
            int seg = idx & 15;
            int cpl = (idx >> 4) & 3;
            int t   = (idx >> 6) & 15;
            int hl  = idx >> 10;
            const u32* base = hl ? wt_lo : wt;
            const u32* src = &base[((long)t * CPG + cic * 4 + cpl) * CoutP + co0 + seg * 4];
            cp16(&w_s[buf * 9216 + hl * 4608 + (t * 4 + cpl) * 72 + seg * 4], src);
        }
    };
    auto compute_chunk = [&](int buf) {
        const ull* ab0 = &a_s[buf * 288 + lm4];
        const u32* wb = &w_s[buf * 9216];
        #pragma unroll
        for (int kyi = 0; kyi < 2; kyi++) {
            const int ky = (1 - py) + 2 * kyi;
            const int t0 = ky * 4 + (1 - px), t1 = t0 + 2;
            u32 bh0[4], bh1[4], bl0[4], bl1[4];
            #pragma unroll
            for (int nf = 0; nf < 4; nf++) {
                const int coi = wn * 32 + nf * 8 + l4;
                bh0[nf] = wb[(t0 * 4 + lm4) * 72 + coi];
                bh1[nf] = wb[(t1 * 4 + lm4) * 72 + coi];
                bl0[nf] = wb[4608 + (t0 * 4 + lm4) * 72 + coi];
                bl1[nf] = wb[4608 + (t1 * 4 + lm4) * 72 + coi];
            }
            #pragma unroll
            for (int rh = 0; rh < 2; rh++) {
                const int pr = rh + 1 + (py == 0 ? -kyi : 1 - kyi);
                ull q00 = ab0[pr * 72 + (pc0 + l4    ) * 4];
                ull q01 = ab0[pr * 72 + (pc0 + l4 + 8) * 4];
                ull q10 = ab0[pr * 72 + (pc1 + l4    ) * 4];
                ull q11 = ab0[pr * 72 + (pc1 + l4 + 8) * 4];
                u32 ah0 = (u32)q00, al0 = (u32)(q00 >> 32);
                u32 ah1 = (u32)q01, al1 = (u32)(q01 >> 32);
                u32 ah2 = (u32)q10, al2 = (u32)(q10 >> 32);
                u32 ah3 = (u32)q11, al3 = (u32)(q11 >> 32);
                #pragma unroll
                for (int nf = 0; nf < 4; nf++)
                    mma16(acc[rh][nf], ah0, ah1, ah2, ah3, bh0[nf], bh1[nf]);
                #pragma unroll
                for (int nf = 0; nf < 4; nf++)
                    mma16(acc[rh][nf], ah0, ah1, ah2, ah3, bl0[nf], bl1[nf]);
                #pragma unroll
                for (int nf = 0; nf < 4; nf++)
                    mma16(acc[rh][nf], al0, al1, al2, al3, bh0[nf], bh1[nf]);
            }
        }
    };

    stage(0, 0);
    asm volatile("cp.async.commit_group;\n" ::: "memory");
    #pragma unroll 1
    for (int cic = 0; cic < nChunk; cic++) {
        if (cic + 1 < nChunk) {
            stage((cic + 1) & 1, cic + 1);
            asm volatile("cp.async.commit_group;\n" ::: "memory");
            asm volatile("cp.async.wait_group 1;\n" ::: "memory");
        } else {
            asm volatile("cp.async.wait_group 0;\n" ::: "memory");
        }
        __syncthreads();
        compute_chunk(cic & 1);
        __syncthreads();
    }

    const int ox = 2 * (X0 + l4) + px;
    #pragma unroll
    for (int rh = 0; rh < 2; rh++) {
        const int oy = 2 * (R0 + rh) + py;
        if (OUT_PACKED) {
            ull* po = (ull*)out_;
            const int CPT = Cout >> 1;
            #pragma unroll
            for (int nf = 0; nf < 4; nf++) {
                const int cob = co0 + wn * 32 + nf * 8 + 2 * lm4;
                const float b0 = bias[cob], b1 = bias[cob + 1];
                const long rowb = (((long)b * CPT + (cob >> 1)) * Hout + oy) * Wout;
                po[rowb + ox]      = packsplit(fmaxf(acc[rh][nf][0] + b0, 0.f),
                                               fmaxf(acc[rh][nf][1] + b1, 0.f));
                po[rowb + ox + 16] = packsplit(fmaxf(acc[rh][nf][2] + b0, 0.f),
                                               fmaxf(acc[rh][nf][3] + b1, 0.f));
            }
        } else {
            float* out = (float*)out_;
            const long outB = (long)b * Cout * Hout * Wout;
            #pragma unroll
            for (int nf = 0; nf < 4; nf++) {
                const int cob = co0 + wn * 32 + nf * 8 + 2 * lm4;
                if (cob < Cout) {
                    const float bv0 = bias[cob];
                    float* o0 = &out[outB + ((long)cob * Hout + oy) * Wout];
                    o0[ox]      = fmaxf(acc[rh][nf][0] + bv0, 0.f);
                    o0[ox + 16] = fmaxf(acc[rh][nf][2] + bv0, 0.f);
                }
                if (cob + 1 < Cout) {
                    const float bv1 = bias[cob + 1];
                    float* o1 = &out[outB + ((long)(cob + 1) * Hout + oy) * Wout];
                    o1[ox]      = fmaxf(acc[rh][nf][1] + bv1, 0.f);
                    o1[ox + 16] = fmaxf(acc[rh][nf][3] + bv1, 0.f);
                }
            }
        }
    }
}

// ---------------------------------------------------------------------------
// Final ConvT layer: Cin=32, Cout=3, tanh (scalar, f32 input).
// ---------------------------------------------------------------------------
__global__ __launch_bounds__(256)
void convt_final_kernel(const float* __restrict__ in, const float* __restrict__ w,
                        const float* __restrict__ bias, float* __restrict__ out)
{
    const int Cin = 32, Hin = 128, Win = 128, Hout = 256, Wout = 256;
    __shared__ float in_s[32][10][11];
    __shared__ float w_s[32][3][16];

    const int tid = threadIdx.x;
    const int b = blockIdx.z;
    const int tx = blockIdx.x & 15;
    const int ty = blockIdx.x >> 4;
    const int oy0 = ty * 16, ox0 = tx * 16;
    const int iyb = oy0 / 2 - 1, ixb = ox0 / 2 - 1;

    for (int i = tid; i < 32 * 3 * 16; i += 256)
        ((float*)w_s)[i] = w[i];
    const float* inb = in + (long)b * Cin * Hin * Win;
    for (int idx = tid; idx < 3200; idx += 256) {
        int c  = idx % 10;
        int r  = (idx / 10) % 10;
        int ci = idx / 100;
        int iy = iyb + r, ix = ixb + c;
        float v = 0.f;
        if (iy >= 0 && iy < Hin && ix >= 0 && ix < Win)
            v = inb[((long)ci * Hin + iy) * Win + ix];
        in_s[ci][r][c] = v;
    }
    __syncthreads();

    const int ox = ox0 + (tid & 15);
    const int oy = oy0 + (tid >> 4);
    const int ky0 = (oy + 1) & 1;
    const int kx0 = (ox + 1) & 1;

    float a0 = bias[0], a1 = bias[1], a2 = bias[2];
    #pragma unroll
    for (int kyi = 0; kyi < 2; kyi++) {
        #pragma unroll
        for (int kxi = 0; kxi < 2; kxi++) {
            const int ky = ky0 + 2 * kyi, kx = kx0 + 2 * kxi;
            const int pr = (oy + 1 - ky) / 2 - iyb;
            const int pc = (ox + 1 - kx) / 2 - ixb;
            const int t = ky * 4 + kx;
            #pragma unroll 8
            for (int ci = 0; ci < 32; ci++) {
                float v = in_s[ci][pr][pc];
                a0 += v * w_s[ci][0][t];
                a1 += v * w_s[ci][1][t];
                a2 += v * w_s[ci][2][t];
            }
        }
    }
    const long o = (long)b * 3 * Hout * Wout + (long)oy * Wout + ox;
    out[o]                    = tanhf(a0);
    out[o + (long)Hout*Wout]  = tanhf(a1);
    out[o + 2L*Hout*Wout]     = tanhf(a2);
}

// ---------------------------------------------------------------------------
// Quantizer (z is f32 NCHW from e4)
// ---------------------------------------------------------------------------
__global__ void e2_kernel(const float* __restrict__ embed, float* __restrict__ e2)
{
    int k = blockIdx.x * blockDim.x + threadIdx.x;
    if (k >= 1024) return;
    const float* e = embed + (long)k * 512;
    float s = 0.f;
    #pragma unroll 4
    for (int d = 0; d < 512; d++) { float v = e[d]; s += v * v; }
    e2[k] = s;
}

__global__ __launch_bounds__(128)
void argmin_kernel(const float* __restrict__ z, const float* __restrict__ embed,
                   const float* __restrict__ e2, int* __restrict__ idx_out)
{
    __shared__ __align__(16) float z_s[512][8];
    __shared__ float rv[8][128];
    __shared__ int   ri[8][128];
    const int tid = threadIdx.x;
    const int n0 = blockIdx.x * 8;
    const int b = n0 >> 8;
    const int pix0 = n0 & 255;
    const float* zb = z + (long)b * 512 * 256 + pix0;

    for (int i = tid; i < 512 * 8; i += 128) {
        int d = i >> 3, nl = i & 7;
        z_s[d][nl] = zb[(long)d * 256 + nl];
    }
    __syncthreads();

    float bv[8]; int bi[8];
    #pragma unroll
    for (int nl = 0; nl < 8; nl++) { bv[nl] = 3.4e38f; bi[nl] = 0; }

    for (int k = tid; k < 1024; k += 128) {
        const float* e = embed + (long)k * 512;
        ull dp[4];
        #pragma unroll
        for (int h = 0; h < 4; h++) dp[h] = 0ull;
        #pragma unroll 4
        for (int d = 0; d < 512; d++) {
            ull ev2 = pack2(e[d]);
            const ull* zp = reinterpret_cast<const ull*>(&z_s[d][0]);
            ffma2(dp[0], ev2, zp[0]); ffma2(dp[1], ev2, zp[1]);
            ffma2(dp[2], ev2, zp[2]); ffma2(dp[3], ev2, zp[3]);
        }
        float c = e2[k];
        #pragma unroll
        for (int h = 0; h < 4; h++) {
            float2 dv = upk(dp[h]);
            float dist0 = c - 2.f * dv.x;
            float dist1 = c - 2.f * dv.y;
            if (dist0 < bv[2*h])   { bv[2*h]   = dist0; bi[2*h]   = k; }
            if (dist1 < bv[2*h+1]) { bv[2*h+1] = dist1; bi[2*h+1] = k; }
        }
    }
    #pragma unroll
    for (int nl = 0; nl < 8; nl++) { rv[nl][tid] = bv[nl]; ri[nl][tid] = bi[nl]; }
    __syncthreads();
    if (tid < 8) {
        float best = rv[tid][0]; int besti = ri[tid][0];
        for (int j = 1; j < 128; j++) {
            float v = rv[tid][j]; int ii = ri[tid][j];
            if (v < best || (v == best && ii < besti)) { best = v; besti = ii; }
        }
        idx_out[n0 + tid] = besti;
    }
}

// gather -> packed zq: u64 [b][cp=256][16][16]
__global__ void gather_kernel(const int* __restrict__ idx, const float* __restrict__ embed,
                              ull* __restrict__ zq)
{
    const int n = blockIdx.x;                   // 8192
    const int b = n >> 8, pix = n & 255;
    const float* e = embed + (long)idx[n] * 512;
    const int d = threadIdx.x;                  // 256 threads = 256 pairs
    zq[((long)b * 256 + d) * 256 + pix] = packsplit(e[2 * d], e[2 * d + 1]);
}

// ---------------------------------------------------------------------------
// Launch
// ---------------------------------------------------------------------------
extern "C" void kernel_launch(void* const* d_in, const int* in_sizes, int n_in,
                              void* d_out, int out_size)
{
    const float* x     = (const float*)d_in[0];
    const float* ew1   = (const float*)d_in[1];
    const float* eb1   = (const float*)d_in[2];
    const float* ew2   = (const float*)d_in[3];
    const float* eb2   = (const float*)d_in[4];
    const float* ew3   = (const float*)d_in[5];
    const float* eb3   = (const float*)d_in[6];
    const float* ew4   = (const float*)d_in[7];
    const float* eb4   = (const float*)d_in[8];
    const float* dw1   = (const float*)d_in[9];
    const float* db1   = (const float*)d_in[10];
    const float* dw2   = (const float*)d_in[11];
    const float* db2   = (const float*)d_in[12];
    const float* dw3   = (const float*)d_in[13];
    const float* db3   = (const float*)d_in[14];
    const float* dw4   = (const float*)d_in[15];
    const float* db4   = (const float*)d_in[16];
    const float* embed = (const float*)d_in[17];
    float* out = (float*)d_out;

    float *A, *B, *e2p; int* idxp; u32* wtp;
    cudaGetSymbolAddress((void**)&A,    g_bufA);
    cudaGetSymbolAddress((void**)&B,    g_bufB);
    cudaGetSymbolAddress((void**)&e2p,  g_e2);
    cudaGetSymbolAddress((void**)&idxp, g_idx);
    cudaGetSymbolAddress((void**)&wtp,  g_wt);
    ull* wt64 = (ull*)wtp;

    const int NB = 32;
    const int ENC_SMEM = 104704;  // (4896 + 8192) u64
    const int DEC_SMEM = 78336;   // 576 u64 + 18432 u32
    static int attr_done = 0;
    if (!attr_done) {
        cudaFuncSetAttribute(conv_enc_mma<false, true>,
                             cudaFuncAttributeMaxDynamicSharedMemorySize, ENC_SMEM);
        cudaFuncSetAttribute(conv_enc_mma<true, true>,
                             cudaFuncAttributeMaxDynamicSharedMemorySize, ENC_SMEM);
        cudaFuncSetAttribute(conv_enc_mma<true, false>,
                             cudaFuncAttributeMaxDynamicSharedMemorySize, ENC_SMEM);
        cudaFuncSetAttribute(convt_mma<true>,
                             cudaFuncAttributeMaxDynamicSharedMemorySize, DEC_SMEM);
        cudaFuncSetAttribute(convt_mma<false>,
                             cudaFuncAttributeMaxDynamicSharedMemorySize, DEC_SMEM);
        attr_done = 1;
    }

    // encoder weights: u64 arrays at wt64 offsets
    ull* w1t  = wt64;              // 16*4*64      =   4096 u64
    ull* w2t  = wt64 + 4096;       // 16*32*128    =  65536
    ull* w3t  = wt64 + 69632;      // 16*64*256    = 262144
    ull* w4t  = wt64 + 331776;     // 16*128*512   = 1048576
    // decoder weights: u32 hi/lo arrays after encoder region (u32 offsets)
    u32* dwt1 = wtp + 2760704;     // 2*16*256*128 = 1048576 u32
    u32* dwt2 = wtp + 3809280;     // 2*16*64*64   =  131072
    u32* dwt3 = wtp + 3940352;     // 2*16*32*64   =   65536

    // ---- interleaved wtrans + encoder (keeps e2 in the ncu -s window) ----
    wtrans_kernel<<<16,   256>>>(ew1, w1t, 3,   64,  4);
    conv_enc_mma<false, true><<<dim3(128, 1, NB), 256, ENC_SMEM>>>(x, w1t, eb1, A, 3,   256, 256, 64,  4);
    wtrans_kernel<<<256,  256>>>(ew2, w2t, 64,  128, 32);
    conv_enc_mma<true,  true><<<dim3(32,  2, NB), 256, ENC_SMEM>>>(A, w2t, eb2, B, 64,  128, 128, 128, 32);
    wtrans_kernel<<<1024, 256>>>(ew3, w3t, 128, 256, 64);
    conv_enc_mma<true,  true><<<dim3(8,   4, NB), 256, ENC_SMEM>>>(B, w3t, eb3, A, 128, 64,  64,  256, 64);
    wtrans_kernel<<<4096, 256>>>(ew4, w4t, 256, 512, 128);
    conv_enc_mma<true,  false><<<dim3(2,  8, NB), 256, ENC_SMEM>>>(A, w4t, eb4, B, 256, 32,  32,  512, 128);

    // ---- decoder weight transposes ----
    wtrans_dec_kernel<<<2048, 256>>>(dw1, dwt1, 512, 128, 128, 256);
    wtrans_dec_kernel<<<256,  256>>>(dw2, dwt2, 128, 64,  64,  64);
    wtrans_dec_kernel<<<128,  256>>>(dw3, dwt3, 64,  32,  64,  32);

    // ---- quantizer ----
    e2_kernel<<<4, 256>>>(embed, e2p);
    argmin_kernel<<<1024, 128>>>(B, embed, e2p, idxp);
    gather_kernel<<<8192, 256>>>(idxp, embed, (ull*)A);     // zq packed in A

    // ---- decoder (B-reuse warps) ----
    convt_mma<true ><<<dim3(8,   2, NB), 256, DEC_SMEM>>>(A, dwt1, db1, B, 512, 16,  16,  128, 128, 256);
    convt_mma<true ><<<dim3(32,  1, NB), 256, DEC_SMEM>>>(B, dwt2, db2, A, 128, 32,  32,  64,  64,  64);
    convt_mma<false><<<dim3(128, 1, NB), 256, DEC_SMEM>>>(A, dwt3, db3, B, 64,  64,  64,  32,  64,  32);
    // d4: (32,128,128)->(3,256,256) + tanh
    convt_final_kernel<<<dim3(256, 1, NB), 256>>>(B, dw4, db4, out);
}

// round 17
// speedup vs baseline: 1.0052x; 1.0052x over previous
#include <cuda_runtime.h>
#include <cuda_bf16.h>
#include <math.h>

typedef unsigned int u32;
typedef unsigned long long ull;

// ---------------------------------------------------------------------------
// Scratch (device globals; no allocation anywhere)
// ---------------------------------------------------------------------------
static __device__ __align__(16) float g_bufA[33554432];   // 134 MB
static __device__ __align__(16) float g_bufB[16777216];   //  67 MB
static __device__ int   g_idx[8192];
static __device__ float g_e2[1024];
static __device__ __align__(16) u32 g_wt[4005888];  // enc u64 + dec u32 weights

// packed f32x2 helpers (scalar paths)
__device__ __forceinline__ void ffma2(ull& d, ull a, ull b) {
    asm("fma.rn.f32x2 %0, %1, %2, %0;" : "+l"(d) : "l"(a), "l"(b));
}
__device__ __forceinline__ ull pack2(float a) {
    ull r; unsigned int ai = __float_as_uint(a);
    asm("mov.b64 %0, {%1, %1};" : "=l"(r) : "r"(ai));
    return r;
}
__device__ __forceinline__ float2 upk(ull v) {
    union { ull u; float2 f; } c; c.u = v; return c.f;
}
__device__ __forceinline__ u32 packbf(float v0, float v1) {
    __nv_bfloat162 t = __floats2bfloat162_rn(v0, v1);
    u32 r; memcpy(&r, &t, 4); return r;
}
// split two f32 into (hi bf16x2, lo bf16x2) packed in one u64
__device__ __forceinline__ ull packsplit(float v0, float v1) {
    __nv_bfloat162 h = __floats2bfloat162_rn(v0, v1);
    float r0 = v0 - __bfloat162float(h.x);
    float r1 = v1 - __bfloat162float(h.y);
    u32 hi; memcpy(&hi, &h, 4);
    u32 lo = packbf(r0, r1);
    return (ull)hi | ((ull)lo << 32);
}
// m16n8k16 row.col bf16 MMA, fp32 accum. (a0,a1,b0)=k0-7, (a2,a3,b1)=k8-15.
__device__ __forceinline__ void mma16(float* c, u32 a0, u32 a1, u32 a2, u32 a3,
                                      u32 b0, u32 b1) {
    asm("mma.sync.aligned.m16n8k16.row.col.f32.bf16.bf16.f32 "
        "{%0,%1,%2,%3}, {%4,%5,%6,%7}, {%8,%9}, {%0,%1,%2,%3};"
        : "+f"(c[0]), "+f"(c[1]), "+f"(c[2]), "+f"(c[3])
        : "r"(a0), "r"(a1), "r"(a2), "r"(a3), "r"(b0), "r"(b1));
}
__device__ __forceinline__ void cp8(void* dst, const void* src, bool ok) {
    u32 da = (u32)__cvta_generic_to_shared(dst);
    asm volatile("cp.async.ca.shared.global [%0], [%1], 8, %2;\n"
                 :: "r"(da), "l"(src), "r"(ok ? 8 : 0));
}
__device__ __forceinline__ void cp16(void* dst, const void* src) {
    u32 da = (u32)__cvta_generic_to_shared(dst);
    asm volatile("cp.async.ca.shared.global [%0], [%1], 16;\n"
                 :: "r"(da), "l"(src));
}

// ---------------------------------------------------------------------------
// Encoder weight transpose -> u64 (hi,lo), layout [t][cout][cp]
// ---------------------------------------------------------------------------
__global__ void wtrans_kernel(const float* __restrict__ w, ull* __restrict__ dst,
                              int Cin, int Cout, int CPG)
{
    const int S = 16 * CPG * Cout;
    int idx = blockIdx.x * 256 + threadIdx.x;
    if (idx >= S) return;
    int cp = idx % CPG;
    int rest = idx / CPG;
    int co = rest % Cout;
    int t  = rest / Cout;
    int ci0 = 2 * cp;
    float v0 = (ci0     < Cin) ? w[((long)co * Cin + ci0    ) * 16 + t] : 0.f;
    float v1 = (ci0 + 1 < Cin) ? w[((long)co * Cin + ci0 + 1) * 16 + t] : 0.f;
    dst[idx] = packsplit(v0, v1);
}

// ---------------------------------------------------------------------------
// Decoder weight transpose (R11 layout): u32 hi at [t][cp][coutP], lo at +S
// ---------------------------------------------------------------------------
__global__ void wtrans_dec_kernel(const float* __restrict__ w, u32* __restrict__ dst,
                                  int Cin, int Cout, int CoutP, int CPG)
{
    const int S = 16 * CPG * CoutP;
    int idx = blockIdx.x * 256 + threadIdx.x;
    if (idx >= S) return;
    int co = idx % CoutP;
    int rest = idx / CoutP;
    int cp = rest % CPG;
    int t  = rest / CPG;
    int ci0 = 2 * cp;
    float v0 = 0.f, v1 = 0.f;
    if (co < Cout) {
        if (ci0     < Cin) v0 = w[((long)ci0       * Cout + co) * 16 + t];
        if (ci0 + 1 < Cin) v1 = w[((long)(ci0 + 1) * Cout + co) * 16 + t];
    }
    ull p = packsplit(v0, v1);
    dst[idx]     = (u32)p;
    dst[S + idx] = (u32)(p >> 32);
}

// ---------------------------------------------------------------------------
// Encoder conv (R15 best; e1 staging unrolled x2 for MLP)
// ---------------------------------------------------------------------------
template<bool IN_PACKED, bool OUT_PACKED>
__global__ __launch_bounds__(256)
void conv_enc_mma(const void* __restrict__ in_, const ull* __restrict__ wt,
                  const float* __restrict__ bias, void* __restrict__ out_,
                  int Cin, int Hin, int Win, int Cout, int CPG)
{
    extern __shared__ ull smdyn[];
    ull* a_s = smdyn;                   // 2 bufs x 2448 u64
    ull* w_s = smdyn + 4896;            // 2 bufs x 4096 u64

    const int Hout = Hin >> 1, Wout = Win >> 1;
    const int tiles_x = Wout >> 4;
    const int tx = blockIdx.x % tiles_x;
    const int ty = blockIdx.x / tiles_x;
    const int OX0 = tx * 16, OY0 = ty * 8;
    const int co0 = blockIdx.y * 64;
    const int b   = blockIdx.z;

    const int tid  = threadIdx.x;
    const int wid  = tid >> 5;
    const int lane = tid & 31;
    const int wm   = wid & 3;
    const int wn   = wid >> 2;
    const int l4   = lane >> 2;
    const int lm4  = lane & 3;

    float acc[2][4][4];
    #pragma unroll
    for (int rh = 0; rh < 2; rh++)
        #pragma unroll
        for (int nf = 0; nf < 4; nf++)
            #pragma unroll
            for (int c = 0; c < 4; c++) acc[rh][nf][c] = 0.f;

    const int nChunk = CPG >> 2;
    const long HW = (long)Hin * Win;

    auto stage_w = [&](int buf, int cic) {
        #pragma unroll 1
        for (int idx = tid; idx < 2048; idx += 256) {
            int seg = idx & 1;
            int co  = (idx >> 1) & 63;
            int t   = idx >> 7;
            const ull* src = &wt[((long)t * Cout + co0 + co) * CPG + cic * 4 + seg * 2];
            cp16(&w_s[buf * 4096 + (t * 64 + co) * 4 + seg * 2], src);
        }
    };
    auto stage_a = [&](int buf, int cic) {
        const ull* pbase = (const ull*)in_ + ((long)b * CPG + cic * 4) * HW;
        #pragma unroll 1
        for (int y = wid; y < 18; y += 8) {
            const int gy = 2 * OY0 - 1 + y;
            const bool okY = (gy >= 0) && (gy < Hin);
            const ull* prow = pbase + (long)gy * Win;
            ull* drow = &a_s[buf * 2448 + y * 68];
            #pragma unroll 1
            for (int e = lane; e < 136; e += 32) {
                int xs = e >> 2, cp = e & 3;
                int gx = 2 * OX0 - 1 + xs;
                bool ok = okY && (gx >= 0) && (gx < Win);
                const ull* src = ok ? (prow + cp * HW + gx) : (const ull*)in_;
                cp8(drow + (xs & 1) * 1224 + (xs >> 1) * 4 + cp, src, ok);
            }
        }
    };
    auto compute_chunk = [&](int buf) {
        const ull* wb = &w_s[buf * 4096 + lm4];
        const ull* abase = &a_s[buf * 2448 + lm4];
        #pragma unroll
        for (int ky = 0; ky < 4; ky++) {
            #pragma unroll
            for (int par = 0; par < 2; par++) {
                const int t0 = ky * 4 + par, t1 = t0 + 2;
                u32 bh0[4], bh1[4], bl0[4], bl1[4];
                #pragma unroll
                for (int nf = 0; nf < 4; nf++) {
                    const int coi = wn * 32 + nf * 8 + l4;
                    ull q0 = wb[(t0 * 64 + coi) * 4];
                    ull q1 = wb[(t1 * 64 + coi) * 4];
                    bh0[nf] = (u32)q0; bl0[nf] = (u32)(q0 >> 32);
                    bh1[nf] = (u32)q1; bl1[nf] = (u32)(q1 >> 32);
                }
                #pragma unroll
                for (int rh = 0; rh < 2; rh++) {
                    const int y = 4 * wm + 2 * rh + ky;
                    const ull* ab = abase + par * 1224 + y * 68;
                    ull p00 = ab[(l4    ) * 4];
                    ull p01 = ab[(l4 + 8) * 4];
                    ull p10 = ab[(l4 + 1) * 4];
                    ull p11 = ab[(l4 + 9) * 4];
                    u32 ah0 = (u32)p00, al0 = (u32)(p00 >> 32);
                    u32 ah1 = (u32)p01, al1 = (u32)(p01 >> 32);
                    u32 ah2 = (u32)p10, al2 = (u32)(p10 >> 32);
                    u32 ah3 = (u32)p11, al3 = (u32)(p11 >> 32);
                    #pragma unroll
                    for (int nf = 0; nf < 4; nf++)
                        mma16(acc[rh][nf], ah0, ah1, ah2, ah3, bh0[nf], bh1[nf]);
                    #pragma unroll
                    for (int nf = 0; nf < 4; nf++)
                        mma16(acc[rh][nf], ah0, ah1, ah2, ah3, bl0[nf], bl1[nf]);
                    #pragma unroll
                    for (int nf = 0; nf < 4; nf++)
                        mma16(acc[rh][nf], al0, al1, al2, al3, bh0[nf], bh1[nf]);
                }
            }
        }
    };

    if (IN_PACKED) {
        stage_a(0, 0); stage_w(0, 0);
        asm volatile("cp.async.commit_group;\n" ::: "memory");
        #pragma unroll 1
        for (int cic = 0; cic < nChunk; cic++) {
            if (cic + 1 < nChunk) {
                stage_a((cic + 1) & 1, cic + 1);
                stage_w((cic + 1) & 1, cic + 1);
                asm volatile("cp.async.commit_group;\n" ::: "memory");
                asm volatile("cp.async.wait_group 1;\n" ::: "memory");
            } else {
                asm volatile("cp.async.wait_group 0;\n" ::: "memory");
            }
            __syncthreads();
            compute_chunk(cic & 1);
            __syncthreads();
        }
    } else {
        stage_w(0, 0);
        asm volatile("cp.async.commit_group;\n" ::: "memory");
        const float* in = (const float*)in_;
        const long inB = (long)b * Cin * HW;
        #pragma unroll 1
        for (int y = wid; y < 18; y += 8) {
            const int gy = 2 * OY0 - 1 + y;
            const bool okY = (gy >= 0) && (gy < Hin);
            ull* drow = &a_s[y * 68];
            #pragma unroll 2
            for (int e = lane; e < 136; e += 32) {
                int xs = e >> 2, cp = e & 3;
                int gx = 2 * OX0 - 1 + xs;
                int ci0 = 2 * cp;
                float v0 = 0.f, v1 = 0.f;
                if (okY && gx >= 0 && gx < Win) {
                    if (ci0     < Cin) v0 = in[inB + (long)ci0       * HW + (long)gy * Win + gx];
                    if (ci0 + 1 < Cin) v1 = in[inB + (long)(ci0 + 1) * HW + (long)gy * Win + gx];
                }
                drow[(xs & 1) * 1224 + (xs >> 1) * 4 + cp] = packsplit(v0, v1);
            }
        }
        asm volatile("cp.async.wait_group 0;\n" ::: "memory");
        __syncthreads();
        compute_chunk(0);
    }

    const int ox0l = OX0 + l4;
    #pragma unroll
    for (int rh = 0; rh < 2; rh++) {
        const int oy = OY0 + 2 * wm + rh;
        if (OUT_PACKED) {
            ull* po = (ull*)out_;
            const int CPT = Cout >> 1;
            #pragma unroll
            for (int nf = 0; nf < 4; nf++) {
                const int cob = co0 + wn * 32 + nf * 8 + 2 * lm4;
                const float b0 = bias[cob], b1 = bias[cob + 1];
                const long rowb = (((long)b * CPT + (cob >> 1)) * Hout + oy) * Wout;
                po[rowb + ox0l]     = packsplit(fmaxf(acc[rh][nf][0] + b0, 0.f),
                                                fmaxf(acc[rh][nf][1] + b1, 0.f));
                po[rowb + ox0l + 8] = packsplit(fmaxf(acc[rh][nf][2] + b0, 0.f),
                                                fmaxf(acc[rh][nf][3] + b1, 0.f));
            }
        } else {
            float* out = (float*)out_;
            const long outB = (long)b * Cout * Hout * Wout;
            #pragma unroll
            for (int nf = 0; nf < 4; nf++) {
                const int cob = co0 + wn * 32 + nf * 8 + 2 * lm4;
                const float b0 = bias[cob], b1 = bias[cob + 1];
                float* o0 = &out[outB + ((long)cob       * Hout + oy) * Wout];
                float* o1 = &out[outB + ((long)(cob + 1) * Hout + oy) * Wout];
                o0[ox0l]     = fmaxf(acc[rh][nf][0] + b0, 0.f);
                o1[ox0l]     = fmaxf(acc[rh][nf][1] + b1, 0.f);
                o0[ox0l + 8] = fmaxf(acc[rh][nf][2] + b0, 0.f);
                o1[ox0l + 8] = fmaxf(acc[rh][nf][3] + b1, 0.f);
            }
        }
    }
}

// ---------------------------------------------------------------------------
// ConvTranspose (R15 version, reverted from R16): 8 warps = 2 rows x 4
// parities; u32 hi/lo W with 72-pad; cp.async; div/mod-free staging.
// ---------------------------------------------------------------------------
template<bool OUT_PACKED>
__global__ __launch_bounds__(256)
void convt_mma(const void* __restrict__ in_, const u32* __restrict__ wt,
               const float* __restrict__ bias, void* __restrict__ out_,
               int Cin, int Hin, int Win, int Cout, int CoutP, int CPG)
{
    extern __shared__ ull smdyn[];
    ull* a_s = smdyn;                   // 2 bufs x 288 u64
    u32* w_s = (u32*)(smdyn + 576);     // 2 bufs x 9216 u32

    const int Hout = Hin * 2, Wout = Win * 2;
    const int tiles_x = Win >> 4;
    const int tx = blockIdx.x % tiles_x;
    const int ry = blockIdx.x / tiles_x;
    const int X0 = tx * 16, R0 = ry * 2;
    const int co0 = blockIdx.y * 64;
    const int b   = blockIdx.z;

    const int tid  = threadIdx.x;
    const int wid  = tid >> 5;
    const int lane = tid & 31;
    const int wm   = wid & 1;
    const int par  = wid >> 1;
    const int py   = par & 1;
    const int px   = par >> 1;
    const int l4   = lane >> 2;
    const int lm4  = lane & 3;

    const u32* wt_lo = wt + 16 * CPG * CoutP;

    float acc[8][4];
    #pragma unroll
    for (int nf = 0; nf < 8; nf++)
        #pragma unroll
        for (int c = 0; c < 4; c++) acc[nf][c] = 0.f;

    const int nChunk = CPG >> 2;
    const int pc0 = (px == 0) ? 1 : 2;
    const int pc1 = (px == 0) ? 0 : 1;
    const long HW = (long)Hin * Win;

    auto stage = [&](int buf, int cic) {
        const ull* pbase = (const ull*)in_ + ((long)b * CPG + cic * 4) * HW;
        {
            const int r = wid & 3;
            const int gy = R0 - 1 + r;
            const bool okY = (gy >= 0) && (gy < Hin);
            const ull* prow = pbase + (long)gy * Win;
            ull* drow = &a_s[buf * 288 + r * 72];
            #pragma unroll 1
            for (int e = (wid >> 2) * 32 + lane; e < 72; e += 64) {
                int cp = e & 3, c = e >> 2;
                int gx = X0 - 1 + c;
                bool ok = okY && (gx >= 0) && (gx < Win);
                const ull* src = ok ? (prow + cp * HW + gx) : (const ull*)in_;
                cp8(drow + c * 4 + cp, src, ok);
            }
        }
        #pragma unroll 1
        for (int idx = tid; idx < 2048; idx += 256) {
            int seg = idx & 15;
            int cpl = (idx >> 4) & 3;
            int t   = (idx >> 6) & 15;
            int hl  = idx >> 10;
            const u32* base = hl ? wt_lo : wt;
            const u32* src = &base[((long)t * CPG + cic * 4 + cpl) * CoutP + co0 + seg * 4];
            cp16(&w_s[buf * 9216 + hl * 4608 + (t * 4 + cpl) * 72 + seg * 4], src);
        }
    };
    auto compute_chunk = [&](int buf) {
        const ull* ab0 = &a_s[buf * 288 + lm4];
        const u32* wb = &w_s[buf * 9216];
        #pragma unroll
        for (int kyi = 0; kyi < 2; kyi++) {
            const int pr = wm + 1 + (py == 0 ? -kyi : 1 - kyi);
            const int ky = (1 - py) + 2 * kyi;
            const int t0 = ky * 4 + (1 - px), t1 = t0 + 2;
            ull q00 = ab0[pr * 72 + (pc0 + l4    ) * 4];
            ull q01 = ab0[pr * 72 + (pc0 + l4 + 8) * 4];
            ull q10 = ab0[pr * 72 + (pc1 + l4    ) * 4];
            ull q11 = ab0[pr * 72 + (pc1 + l4 + 8) * 4];
            u32 ah0 = (u32)q00, al0 = (u32)(q00 >> 32);
            u32 ah1 = (u32)q01, al1 = (u32)(q01 >> 32);
            u32 ah2 = (u32)q10, al2 = (u32)(q10 >> 32);
            u32 ah3 = (u32)q11, al3 = (u32)(q11 >> 32);
            #pragma unroll
            for (int nf = 0; nf < 8; nf++) {
                const int coi = nf * 8 + l4;
                u32 bh0 = wb[(t0 * 4 + lm4) * 72 + coi];
                u32 bh1 = wb[(t1 * 4 + lm4) * 72 + coi];
                u32 bl0 = wb[4608 + (t0 * 4 + lm4) * 72 + coi];
                u32 bl1 = wb[4608 + (t1 * 4 + lm4) * 72 + coi];
                mma16(acc[nf], ah0, ah1, ah2, ah3, bh0, bh1);
                mma16(acc[nf], ah0, ah1, ah2, ah3, bl0, bl1);
                mma16(acc[nf], al0, al1, al2, al3, bh0, bh1);
            }
        }
    };

    stage(0, 0);
    asm volatile("cp.async.commit_group;\n" ::: "memory");
    #pragma unroll 1
    for (int cic = 0; cic < nChunk; cic++) {
        if (cic + 1 < nChunk) {
            stage((cic + 1) & 1, cic + 1);
            asm volatile("cp.async.commit_group;\n" ::: "memory");
            asm volatile("cp.async.wait_group 1;\n" ::: "memory");
        } else {
            asm volatile("cp.async.wait_group 0;\n" ::: "memory");
        }
        __syncthreads();
        compute_chunk(cic & 1);
        __syncthreads();
    }

    const int oy = 2 * (R0 + wm) + py;
    const int ox = 2 * (X0 + l4) + px;
    if (OUT_PACKED) {
        ull* po = (ull*)out_;
        const int CPT = Cout >> 1;
        #pragma unroll
        for (int nf = 0; nf < 8; nf++) {
            const int cob = co0 + nf * 8 + 2 * lm4;
            const float b0 = bias[cob], b1 = bias[cob + 1];
            const long rowb = (((long)b * CPT + (cob >> 1)) * Hout + oy) * Wout;
            po[rowb + ox]      = packsplit(fmaxf(acc[nf][0] + b0, 0.f),
                                           fmaxf(acc[nf][1] + b1, 0.f));
            po[rowb + ox + 16] = packsplit(fmaxf(acc[nf][2] + b0, 0.f),
                                           fmaxf(acc[nf][3] + b1, 0.f));
        }
    } else {
        float* out = (float*)out_;
        const long outB = (long)b * Cout * Hout * Wout;
        #pragma unroll
        for (int nf = 0; nf < 8; nf++) {
            const int cob = co0 + nf * 8 + 2 * lm4;
            if (cob < Cout) {
                const float bv0 = bias[cob];
                float* o0 = &out[outB + ((long)cob * Hout + oy) * Wout];
                o0[ox]      = fmaxf(acc[nf][0] + bv0, 0.f);
                o0[ox + 16] = fmaxf(acc[nf][2] + bv0, 0.f);
            }
            if (cob + 1 < Cout) {
                const float bv1 = bias[cob + 1];
                float* o1 = &out[outB + ((long)(cob + 1) * Hout + oy) * Wout];
                o1[ox]      = fmaxf(acc[nf][1] + bv1, 0.f);
                o1[ox + 16] = fmaxf(acc[nf][3] + bv1, 0.f);
            }
        }
    }
}

// ---------------------------------------------------------------------------
// Final ConvT layer: Cin=32, Cout=3, tanh (scalar, f32 input).
// ---------------------------------------------------------------------------
__global__ __launch_bounds__(256)
void convt_final_kernel(const float* __restrict__ in, const float* __restrict__ w,
                        const float* __restrict__ bias, float* __restrict__ out)
{
    const int Cin = 32, Hin = 128, Win = 128, Hout = 256, Wout = 256;
    __shared__ float in_s[32][10][11];
    __shared__ float w_s[32][3][16];

    const int tid = threadIdx.x;
    const int b = blockIdx.z;
    const int tx = blockIdx.x & 15;
    const int ty = blockIdx.x >> 4;
    const int oy0 = ty * 16, ox0 = tx * 16;
    const int iyb = oy0 / 2 - 1, ixb = ox0 / 2 - 1;

    for (int i = tid; i < 32 * 3 * 16; i += 256)
        ((float*)w_s)[i] = w[i];
    const float* inb = in + (long)b * Cin * Hin * Win;
    for (int idx = tid; idx < 3200; idx += 256) {
        int c  = idx % 10;
        int r  = (idx / 10) % 10;
        int ci = idx / 100;
        int iy = iyb + r, ix = ixb + c;
        float v = 0.f;
        if (iy >= 0 && iy < Hin && ix >= 0 && ix < Win)
            v = inb[((long)ci * Hin + iy) * Win + ix];
        in_s[ci][r][c] = v;
    }
    __syncthreads();

    const int ox = ox0 + (tid & 15);
    const int oy = oy0 + (tid >> 4);
    const int ky0 = (oy + 1) & 1;
    const int kx0 = (ox + 1) & 1;

    float a0 = bias[0], a1 = bias[1], a2 = bias[2];
    #pragma unroll
    for (int kyi = 0; kyi < 2; kyi++) {
        #pragma unroll
        for (int kxi = 0; kxi < 2; kxi++) {
            const int ky = ky0 + 2 * kyi, kx = kx0 + 2 * kxi;
            const int pr = (oy + 1 - ky) / 2 - iyb;
            const int pc = (ox + 1 - kx) / 2 - ixb;
            const int t = ky * 4 + kx;
            #pragma unroll 8
            for (int ci = 0; ci < 32; ci++) {
                float v = in_s[ci][pr][pc];
                a0 += v * w_s[ci][0][t];
                a1 += v * w_s[ci][1][t];
                a2 += v * w_s[ci][2][t];
            }
        }
    }
    const long o = (long)b * 3 * Hout * Wout + (long)oy * Wout + ox;
    out[o]                    = tanhf(a0);
    out[o + (long)Hout*Wout]  = tanhf(a1);
    out[o + 2L*Hout*Wout]     = tanhf(a2);
}

// ---------------------------------------------------------------------------
// Quantizer (z is f32 NCHW from e4)
// ---------------------------------------------------------------------------
__global__ void e2_kernel(const float* __restrict__ embed, float* __restrict__ e2)
{
    int k = blockIdx.x * blockDim.x + threadIdx.x;
    if (k >= 1024) return;
    const float* e = embed + (long)k * 512;
    float s = 0.f;
    #pragma unroll 4
    for (int d = 0; d < 512; d++) { float v = e[d]; s += v * v; }
    e2[k] = s;
}

__global__ __launch_bounds__(128)
void argmin_kernel(const float* __restrict__ z, const float* __restrict__ embed,
                   const float* __restrict__ e2, int* __restrict__ idx_out)
{
    __shared__ __align__(16) float z_s[512][8];
    __shared__ float rv[8][128];
    __shared__ int   ri[8][128];
    const int tid = threadIdx.x;
    const int n0 = blockIdx.x * 8;
    const int b = n0 >> 8;
    const int pix0 = n0 & 255;
    const float* zb = z + (long)b * 512 * 256 + pix0;

    for (int i = tid; i < 512 * 8; i += 128) {
        int d = i >> 3, nl = i & 7;
        z_s[d][nl] = zb[(long)d * 256 + nl];
    }
    __syncthreads();

    float bv[8]; int bi[8];
    #pragma unroll
    for (int nl = 0; nl < 8; nl++) { bv[nl] = 3.4e38f; bi[nl] = 0; }

    for (int k = tid; k < 1024; k += 128) {
        const float* e = embed + (long)k * 512;
        ull dp[4];
        #pragma unroll
        for (int h = 0; h < 4; h++) dp[h] = 0ull;
        #pragma unroll 4
        for (int d = 0; d < 512; d++) {
            ull ev2 = pack2(e[d]);
            const ull* zp = reinterpret_cast<const ull*>(&z_s[d][0]);
            ffma2(dp[0], ev2, zp[0]); ffma2(dp[1], ev2, zp[1]);
            ffma2(dp[2], ev2, zp[2]); ffma2(dp[3], ev2, zp[3]);
        }
        float c = e2[k];
        #pragma unroll
        for (int h = 0; h < 4; h++) {
            float2 dv = upk(dp[h]);
            float dist0 = c - 2.f * dv.x;
            float dist1 = c - 2.f * dv.y;
            if (dist0 < bv[2*h])   { bv[2*h]   = dist0; bi[2*h]   = k; }
            if (dist1 < bv[2*h+1]) { bv[2*h+1] = dist1; bi[2*h+1] = k; }
        }
    }
    #pragma unroll
    for (int nl = 0; nl < 8; nl++) { rv[nl][tid] = bv[nl]; ri[nl][tid] = bi[nl]; }
    __syncthreads();
    if (tid < 8) {
        float best = rv[tid][0]; int besti = ri[tid][0];
        for (int j = 1; j < 128; j++) {
            float v = rv[tid][j]; int ii = ri[tid][j];
            if (v < best || (v == best && ii < besti)) { best = v; besti = ii; }
        }
        idx_out[n0 + tid] = besti;
    }
}

// gather -> packed zq: u64 [b][cp=256][16][16]
__global__ void gather_kernel(const int* __restrict__ idx, const float* __restrict__ embed,
                              ull* __restrict__ zq)
{
    const int n = blockIdx.x;                   // 8192
    const int b = n >> 8, pix = n & 255;
    const float* e = embed + (long)idx[n] * 512;
    const int d = threadIdx.x;                  // 256 threads = 256 pairs
    zq[((long)b * 256 + d) * 256 + pix] = packsplit(e[2 * d], e[2 * d + 1]);
}

// ---------------------------------------------------------------------------
// Launch
// ---------------------------------------------------------------------------
extern "C" void kernel_launch(void* const* d_in, const int* in_sizes, int n_in,
                              void* d_out, int out_size)
{
    const float* x     = (const float*)d_in[0];
    const float* ew1   = (const float*)d_in[1];
    const float* eb1   = (const float*)d_in[2];
    const float* ew2   = (const float*)d_in[3];
    const float* eb2   = (const float*)d_in[4];
    const float* ew3   = (const float*)d_in[5];
    const float* eb3   = (const float*)d_in[6];
    const float* ew4   = (const float*)d_in[7];
    const float* eb4   = (const float*)d_in[8];
    const float* dw1   = (const float*)d_in[9];
    const float* db1   = (const float*)d_in[10];
    const float* dw2   = (const float*)d_in[11];
    const float* db2   = (const float*)d_in[12];
    const float* dw3   = (const float*)d_in[13];
    const float* db3   = (const float*)d_in[14];
    const float* dw4   = (const float*)d_in[15];
    const float* db4   = (const float*)d_in[16];
    const float* embed = (const float*)d_in[17];
    float* out = (float*)d_out;

    float *A, *B, *e2p; int* idxp; u32* wtp;
    cudaGetSymbolAddress((void**)&A,    g_bufA);
    cudaGetSymbolAddress((void**)&B,    g_bufB);
    cudaGetSymbolAddress((void**)&e2p,  g_e2);
    cudaGetSymbolAddress((void**)&idxp, g_idx);
    cudaGetSymbolAddress((void**)&wtp,  g_wt);
    ull* wt64 = (ull*)wtp;

    const int NB = 32;
    const int ENC_SMEM = 104704;  // (4896 + 8192) u64
    const int DEC_SMEM = 78336;   // 576 u64 + 18432 u32
    static int attr_done = 0;
    if (!attr_done) {
        cudaFuncSetAttribute(conv_enc_mma<false, true>,
                             cudaFuncAttributeMaxDynamicSharedMemorySize, ENC_SMEM);
        cudaFuncSetAttribute(conv_enc_mma<true, true>,
                             cudaFuncAttributeMaxDynamicSharedMemorySize, ENC_SMEM);
        cudaFuncSetAttribute(conv_enc_mma<true, false>,
                             cudaFuncAttributeMaxDynamicSharedMemorySize, ENC_SMEM);
        cudaFuncSetAttribute(convt_mma<true>,
                             cudaFuncAttributeMaxDynamicSharedMemorySize, DEC_SMEM);
        cudaFuncSetAttribute(convt_mma<false>,
                             cudaFuncAttributeMaxDynamicSharedMemorySize, DEC_SMEM);
        attr_done = 1;
    }

    // encoder weights: u64 arrays at wt64 offsets
    ull* w1t  = wt64;              // 16*4*64      =   4096 u64
    ull* w2t  = wt64 + 4096;       // 16*32*128    =  65536
    ull* w3t  = wt64 + 69632;      // 16*64*256    = 262144
    ull* w4t  = wt64 + 331776;     // 16*128*512   = 1048576
    // decoder weights: u32 hi/lo arrays after encoder region (u32 offsets)
    u32* dwt1 = wtp + 2760704;     // 2*16*256*128 = 1048576 u32
    u32* dwt2 = wtp + 3809280;     // 2*16*64*64   =  131072
    u32* dwt3 = wtp + 3940352;     // 2*16*32*64   =   65536

    // ---- interleaved wtrans + encoder (keeps e2 in the ncu -s window) ----
    wtrans_kernel<<<16,   256>>>(ew1, w1t, 3,   64,  4);
    conv_enc_mma<false, true><<<dim3(128, 1, NB), 256, ENC_SMEM>>>(x, w1t, eb1, A, 3,   256, 256, 64,  4);
    wtrans_kernel<<<256,  256>>>(ew2, w2t, 64,  128, 32);
    conv_enc_mma<true,  true><<<dim3(32,  2, NB), 256, ENC_SMEM>>>(A, w2t, eb2, B, 64,  128, 128, 128, 32);
    wtrans_kernel<<<1024, 256>>>(ew3, w3t, 128, 256, 64);
    conv_enc_mma<true,  true><<<dim3(8,   4, NB), 256, ENC_SMEM>>>(B, w3t, eb3, A, 128, 64,  64,  256, 64);
    wtrans_kernel<<<4096, 256>>>(ew4, w4t, 256, 512, 128);
    conv_enc_mma<true,  false><<<dim3(2,  8, NB), 256, ENC_SMEM>>>(A, w4t, eb4, B, 256, 32,  32,  512, 128);

    // ---- decoder weight transposes ----
    wtrans_dec_kernel<<<2048, 256>>>(dw1, dwt1, 512, 128, 128, 256);
    wtrans_dec_kernel<<<256,  256>>>(dw2, dwt2, 128, 64,  64,  64);
    wtrans_dec_kernel<<<128,  256>>>(dw3, dwt3, 64,  32,  64,  32);

    // ---- quantizer ----
    e2_kernel<<<4, 256>>>(embed, e2p);
    argmin_kernel<<<1024, 128>>>(B, embed, e2p, idxp);
    gather_kernel<<<8192, 256>>>(idxp, embed, (ull*)A);     // zq packed in A

    // ---- decoder (R15 kernels) ----
    convt_mma<true ><<<dim3(8,   2, NB), 256, DEC_SMEM>>>(A, dwt1, db1, B, 512, 16,  16,  128, 128, 256);
    convt_mma<true ><<<dim3(32,  1, NB), 256, DEC_SMEM>>>(B, dwt2, db2, A, 128, 32,  32,  64,  64,  64);
    convt_mma<false><<<dim3(128, 1, NB), 256, DEC_SMEM>>>(A, dwt3, db3, B, 64,  64,  64,  32,  64,  32);
    // d4: (32,128,128)->(3,256,256) + tanh
    convt_final_kernel<<<dim3(256, 1, NB), 256>>>(B, dw4, db4, out);
}